// round 12
// baseline (speedup 1.0000x reference)
#include <cstdint>
#include <type_traits>
#include <cuda_runtime.h>
#include <cuda_fp16.h>
#include <mma.h>

using namespace nvcuda;

// Problem constants
#define Mrows 16384
#define QKV_N 3072
#define Dn 1024

// Scratch (device globals: allocation-free)
__device__ __half g_qkvh[(size_t)Mrows * QKV_N];   // 96 MB  (fp16 qkv)
__device__ __half g_attnh[(size_t)Mrows * Dn];     // 32 MB  (fp16 attention out)
__device__ __half g_xh[(size_t)Mrows * Dn];        // 32 MB  (fp16 x)
__device__ __half g_wqkvh[(size_t)Dn * QKV_N];     // 6 MB   (fp16 Wqkv)
__device__ __half g_wouth[(size_t)Dn * Dn];        // 2 MB   (fp16 Wout)

__device__ __forceinline__ void cp_async16(__half* smem_dst, const __half* gmem_src) {
    unsigned s = (unsigned)__cvta_generic_to_shared(smem_dst);
    asm volatile("cp.async.cg.shared.global [%0], [%1], 16;\n" :: "r"(s), "l"(gmem_src));
}
__device__ __forceinline__ void cp_commit() {
    asm volatile("cp.async.commit_group;\n" ::);
}
template<int N>
__device__ __forceinline__ void cp_wait() {
    asm volatile("cp.async.wait_group %0;\n" :: "n"(N));
}

// ---------------------------------------------------------------------------
// FP16 WMMA GEMM (fp32 accumulate), 3-stage cp.async pipeline.
// Block tile 128x128, BK=64, 4 warps (2x2), warp tile 64x64, 128 threads,
// 2 CTAs/SM. Single barrier per K-tile; cp.async interleaved with MMA;
// fragment DOUBLE-BUFFERING across kk (LDSM latency hidden behind HMMA).
// ---------------------------------------------------------------------------
#define BM 128
#define BN 128
#define BK 64
#define STAGES 3
#define A_LD (BK + 8)            // 72 halves
#define B_LD (BN + 8)            // 136 halves
#define A_STAGE (BM * A_LD)      // 9216 halves
#define B_STAGE (BK * B_LD)      // 8704 halves
#define SMEM_HALVES (STAGES * (A_STAGE + B_STAGE))
#define SMEM_BYTES (SMEM_HALVES * 2)   // 107520 B (x2 CTAs = 215KB < 228KB)

template<typename OutT>
__global__ __launch_bounds__(128, 2)
void gemm_fp16_pipe_kernel(const __half* __restrict__ A,
                           const __half* __restrict__ B,
                           OutT* __restrict__ C,
                           int M, int N, int K)
{
    extern __shared__ __half smem[];
    __half* As = smem;                         // [STAGES][BM][A_LD]
    __half* Bs = smem + STAGES * A_STAGE;      // [STAGES][BK][B_LD]

    const int tid = threadIdx.x;
    const int warpId = tid >> 5;
    const int warpRow = warpId >> 1;      // 0..1  (64 rows each)
    const int warpCol = warpId & 1;       // 0..1  (64 cols each)

    const int rowBase = blockIdx.y * BM;
    const int colBase = blockIdx.x * BN;

    const int KT = K / BK;

    auto load_stage_full = [&](int kt, int stage) {
        const __half* Ag = A + (size_t)rowBase * K + kt * BK;
        const __half* Bg = B + (size_t)(kt * BK) * N + colBase;
        __half* Asm = As + stage * A_STAGE;
        __half* Bsm = Bs + stage * B_STAGE;
        #pragma unroll
        for (int i = 0; i < 8; i++) {
            int l = tid + i * 128;
            int ar = l >> 3, ac = (l & 7) << 3;
            cp_async16(Asm + ar * A_LD + ac, Ag + (size_t)ar * K + ac);
        }
        #pragma unroll
        for (int i = 0; i < 8; i++) {
            int l = tid + i * 128;
            int br = l >> 4, bc = (l & 15) << 3;
            cp_async16(Bsm + br * B_LD + bc, Bg + (size_t)br * N + bc);
        }
        cp_commit();
    };

    auto load_stage_part = [&](int kt, int stage, int part) {
        __half* Asm = As + stage * A_STAGE;
        __half* Bsm = Bs + stage * B_STAGE;
        if (part < 2) {
            const __half* Ag = A + (size_t)rowBase * K + kt * BK;
            #pragma unroll
            for (int i = 0; i < 4; i++) {
                int l = tid + (part * 4 + i) * 128;
                int ar = l >> 3, ac = (l & 7) << 3;
                cp_async16(Asm + ar * A_LD + ac, Ag + (size_t)ar * K + ac);
            }
        } else {
            const __half* Bg = B + (size_t)(kt * BK) * N + colBase;
            #pragma unroll
            for (int i = 0; i < 4; i++) {
                int l = tid + ((part - 2) * 4 + i) * 128;
                int br = l >> 4, bc = (l & 15) << 3;
                cp_async16(Bsm + br * B_LD + bc, Bg + (size_t)br * N + bc);
            }
        }
    };

    load_stage_full(0, 0);
    load_stage_full(1, 1);

    wmma::fragment<wmma::accumulator, 16, 16, 16, float> acc[4][4];
    #pragma unroll
    for (int m = 0; m < 4; m++)
        #pragma unroll
        for (int n = 0; n < 4; n++)
            wmma::fill_fragment(acc[m][n], 0.0f);

    // Double-buffered operand fragments
    wmma::fragment<wmma::matrix_a, 16, 16, 16, __half, wmma::row_major> af[2][4];
    wmma::fragment<wmma::matrix_b, 16, 16, 16, __half, wmma::row_major> bf[2][4];

    for (int kt = 0; kt < KT; kt++) {
        cp_wait<STAGES - 2>();
        __syncthreads();   // single barrier per K-tile

        const bool doLoad = (kt + STAGES - 1 < KT);
        const int  ldStage = (kt + STAGES - 1) % STAGES;

        const __half* Asm = As + (kt % STAGES) * A_STAGE;
        const __half* Bsm = Bs + (kt % STAGES) * B_STAGE;

        // Prime fragment buffer 0 with kk=0
        #pragma unroll
        for (int m = 0; m < 4; m++)
            wmma::load_matrix_sync(af[0][m], Asm + (warpRow * 64 + m * 16) * A_LD, A_LD);
        #pragma unroll
        for (int n = 0; n < 4; n++)
            wmma::load_matrix_sync(bf[0][n], Bsm + warpCol * 64 + n * 16, B_LD);

        #pragma unroll
        for (int kk = 0; kk < BK / 16; kk++) {
            const int cur = kk & 1, nxt = cur ^ 1;

            // Prefetch kk+1's fragments into the alternate buffer
            if (kk + 1 < BK / 16) {
                #pragma unroll
                for (int m = 0; m < 4; m++)
                    wmma::load_matrix_sync(af[nxt][m],
                        Asm + (warpRow * 64 + m * 16) * A_LD + (kk + 1) * 16, A_LD);
                #pragma unroll
                for (int n = 0; n < 4; n++)
                    wmma::load_matrix_sync(bf[nxt][n],
                        Bsm + ((kk + 1) * 16) * B_LD + warpCol * 64 + n * 16, B_LD);
            }

            // Interleave a quarter of the next-stage cp.async loads
            if (doLoad)
                load_stage_part(kt + STAGES - 1, ldStage, kk);

            #pragma unroll
            for (int m = 0; m < 4; m++)
                #pragma unroll
                for (int n = 0; n < 4; n++)
                    wmma::mma_sync(acc[m][n], af[cur][m], bf[cur][n], acc[m][n]);
        }
        cp_commit();
    }

    // Epilogue
    #pragma unroll
    for (int m = 0; m < 4; m++) {
        #pragma unroll
        for (int n = 0; n < 4; n++) {
            int r = rowBase + warpRow * 64 + m * 16;
            int c = colBase + warpCol * 64 + n * 16;
            if constexpr (std::is_same<OutT, __half>::value) {
                wmma::fragment<wmma::accumulator, 16, 16, 16, __half> hacc;
                #pragma unroll
                for (int t = 0; t < hacc.num_elements; t++)
                    hacc.x[t] = __float2half_rn(acc[m][n].x[t]);
                wmma::store_matrix_sync(C + (size_t)r * N + c, hacc, N, wmma::mem_row_major);
            } else {
                wmma::store_matrix_sync(C + (size_t)r * N + c, acc[m][n], N, wmma::mem_row_major);
            }
        }
    }
}

// ---------------------------------------------------------------------------
// Elementwise fp32 -> fp16 (RN) conversion
// ---------------------------------------------------------------------------
__global__ void f32_to_f16_kernel(const float4* __restrict__ in,
                                  __half2* __restrict__ out, int n4)
{
    int i = blockIdx.x * blockDim.x + threadIdx.x;
    if (i < n4) {
        float4 v = in[i];
        out[2 * i]     = __floats2half2_rn(v.x, v.y);
        out[2 * i + 1] = __floats2half2_rn(v.z, v.w);
    }
}

// ---------------------------------------------------------------------------
// Per-token head-attention: fp16 qkv in, fp32 math, fp16 out.
// ---------------------------------------------------------------------------
#define QK_LD 17   // float4 stride for sq/sk rows

__global__ __launch_bounds__(256, 8)
void attn_kernel(const __half* __restrict__ qkv, __half* __restrict__ out)
{
    __shared__ float4 sq[16 * QK_LD];
    __shared__ float4 sk[16 * QK_LD];
    __shared__ float4 sv[16 * 16];
    __shared__ float  sattn[16 * 16];

    const int t = blockIdx.x;
    const uint4* base8 = reinterpret_cast<const uint4*>(qkv + (size_t)t * QKV_N);
    const int tid = threadIdx.x;

    #pragma unroll
    for (int c = 0; c < 2; c++) {
        int idx8 = tid + c * 256;
        if (idx8 < 384) {
            uint4 raw = base8[idx8];
            const __half2* h2 = reinterpret_cast<const __half2*>(&raw);
            float2 f0 = __half22float2(h2[0]);
            float2 f1 = __half22float2(h2[1]);
            float2 f2 = __half22float2(h2[2]);
            float2 f3 = __half22float2(h2[3]);
            float4 va = make_float4(f0.x, f0.y, f1.x, f1.y);
            float4 vb = make_float4(f2.x, f2.y, f3.x, f3.y);
            int arr = idx8 >> 7;
            int loc = idx8 & 127;
            int r   = loc >> 3;
            int d8  = loc & 7;
            if (arr == 0) {
                sq[r * QK_LD + d8 * 2]     = va;
                sq[r * QK_LD + d8 * 2 + 1] = vb;
            } else if (arr == 1) {
                sk[r * QK_LD + d8 * 2]     = va;
                sk[r * QK_LD + d8 * 2 + 1] = vb;
            } else {
                sv[r * 16 + d8 * 2]     = va;
                sv[r * 16 + d8 * 2 + 1] = vb;
            }
        }
    }
    __syncthreads();

    const int i = tid >> 4, j = tid & 15;
    float s = 0.0f;
    #pragma unroll
    for (int d4 = 0; d4 < 16; d4++) {
        float4 a = sq[i * QK_LD + d4];
        float4 b = sk[j * QK_LD + d4];
        s += a.x * b.x + a.y * b.y + a.z * b.z + a.w * b.w;
    }
    s *= 0.125f;

    float mx = s;
    #pragma unroll
    for (int off = 8; off; off >>= 1)
        mx = fmaxf(mx, __shfl_xor_sync(0xffffffffu, mx, off));
    float e = __expf(s - mx);
    float sum = e;
    #pragma unroll
    for (int off = 8; off; off >>= 1)
        sum += __shfl_xor_sync(0xffffffffu, sum, off);
    sattn[i * 16 + j] = e / sum;
    __syncthreads();

    const int oi = tid >> 4, od4 = tid & 15;
    float4 acc = make_float4(0.f, 0.f, 0.f, 0.f);
    #pragma unroll
    for (int jj = 0; jj < 16; jj++) {
        float w = sattn[oi * 16 + jj];
        float4 v = sv[jj * 16 + od4];
        acc.x += w * v.x; acc.y += w * v.y;
        acc.z += w * v.z; acc.w += w * v.w;
    }
    __half2* o2 = reinterpret_cast<__half2*>(out + (size_t)t * Dn + oi * 64 + od4 * 4);
    o2[0] = __floats2half2_rn(acc.x, acc.y);
    o2[1] = __floats2half2_rn(acc.z, acc.w);
}

// ---------------------------------------------------------------------------
extern "C" void kernel_launch(void* const* d_in, const int* in_sizes, int n_in,
                              void* d_out, int out_size)
{
    const float* x    = (const float*)d_in[0];
    const float* Wqkv = (const float*)d_in[1];
    const float* Wout = (const float*)d_in[2];
    float* out = (float*)d_out;

    __half *qkvh_p, *attnh_p, *xh_p, *wqkvh_p, *wouth_p;
    cudaGetSymbolAddress((void**)&qkvh_p, g_qkvh);
    cudaGetSymbolAddress((void**)&attnh_p, g_attnh);
    cudaGetSymbolAddress((void**)&xh_p, g_xh);
    cudaGetSymbolAddress((void**)&wqkvh_p, g_wqkvh);
    cudaGetSymbolAddress((void**)&wouth_p, g_wouth);

    static bool attr_set = false;
    if (!attr_set) {
        cudaFuncSetAttribute(gemm_fp16_pipe_kernel<__half>,
                             cudaFuncAttributeMaxDynamicSharedMemorySize, SMEM_BYTES);
        cudaFuncSetAttribute(gemm_fp16_pipe_kernel<float>,
                             cudaFuncAttributeMaxDynamicSharedMemorySize, SMEM_BYTES);
        attr_set = true;
    }

    // Convert operands to fp16 (RN) once.
    {
        int n4x = (Mrows * Dn) / 4;
        f32_to_f16_kernel<<<(n4x + 255) / 256, 256>>>((const float4*)x, (__half2*)xh_p, n4x);
        int n4q = (Dn * QKV_N) / 4;
        f32_to_f16_kernel<<<(n4q + 255) / 256, 256>>>((const float4*)Wqkv, (__half2*)wqkvh_p, n4q);
        int n4o = (Dn * Dn) / 4;
        f32_to_f16_kernel<<<(n4o + 255) / 256, 256>>>((const float4*)Wout, (__half2*)wouth_p, n4o);
    }

    // GEMM1: qkv = x @ Wqkv   (16384 x 3072, K=1024), fp16 out
    {
        dim3 grid(QKV_N / BN, Mrows / BM);
        gemm_fp16_pipe_kernel<__half><<<grid, 128, SMEM_BYTES>>>(xh_p, wqkvh_p, qkvh_p,
                                                                 Mrows, QKV_N, Dn);
    }

    // Attention per token (fp16 in, fp32 math, fp16 out)
    attn_kernel<<<Mrows, 256>>>(qkvh_p, attnh_p);

    // GEMM2: out = attn @ Wout  (16384 x 1024, K=1024), fp32 out
    {
        dim3 grid(Dn / BN, Mrows / BM);
        gemm_fp16_pipe_kernel<float><<<grid, 128, SMEM_BYTES>>>(attnh_p, wouth_p, out,
                                                                Mrows, Dn, Dn);
    }
}

// round 13
// speedup vs baseline: 1.0845x; 1.0845x over previous
#include <cstdint>
#include <type_traits>
#include <cuda_runtime.h>
#include <cuda_fp16.h>
#include <mma.h>

using namespace nvcuda;

// Problem constants
#define Mrows 16384
#define QKV_N 3072
#define Dn 1024

// Scratch (device globals: allocation-free)
__device__ __half g_qkvh[(size_t)Mrows * QKV_N];   // 96 MB  (fp16 qkv)
__device__ __half g_attnh[(size_t)Mrows * Dn];     // 32 MB  (fp16 attention out)
__device__ __half g_xh[(size_t)Mrows * Dn];        // 32 MB  (fp16 x)
__device__ __half g_wqkvh[(size_t)Dn * QKV_N];     // 6 MB   (fp16 Wqkv)
__device__ __half g_wouth[(size_t)Dn * Dn];        // 2 MB   (fp16 Wout)

__device__ __forceinline__ void cp_async16(__half* smem_dst, const __half* gmem_src) {
    unsigned s = (unsigned)__cvta_generic_to_shared(smem_dst);
    asm volatile("cp.async.cg.shared.global [%0], [%1], 16;\n" :: "r"(s), "l"(gmem_src));
}
__device__ __forceinline__ void cp_commit() {
    asm volatile("cp.async.commit_group;\n" ::);
}
template<int N>
__device__ __forceinline__ void cp_wait() {
    asm volatile("cp.async.wait_group %0;\n" :: "n"(N));
}

// ---------------------------------------------------------------------------
// FP16 WMMA GEMM (fp32 accumulate), 3-stage cp.async pipeline.
// Block tile 128x128, BK=64, 4 warps (2x2), warp tile 64x64, 128 threads,
// 2 CTAs/SM. Single barrier per K-tile; cp.async interleaved with MMA.
// (R11 inner loop — fragment double-buffering reverted.)
// ---------------------------------------------------------------------------
#define BM 128
#define BN 128
#define BK 64
#define STAGES 3
#define A_LD (BK + 8)            // 72 halves
#define B_LD (BN + 8)            // 136 halves
#define A_STAGE (BM * A_LD)      // 9216 halves
#define B_STAGE (BK * B_LD)      // 8704 halves
#define SMEM_HALVES (STAGES * (A_STAGE + B_STAGE))
#define SMEM_BYTES (SMEM_HALVES * 2)   // 107520 B (x2 CTAs = 215KB < 228KB)

template<typename OutT>
__global__ __launch_bounds__(128, 2)
void gemm_fp16_pipe_kernel(const __half* __restrict__ A,
                           const __half* __restrict__ B,
                           OutT* __restrict__ C,
                           int M, int N, int K)
{
    extern __shared__ __half smem[];
    __half* As = smem;                         // [STAGES][BM][A_LD]
    __half* Bs = smem + STAGES * A_STAGE;      // [STAGES][BK][B_LD]

    const int tid = threadIdx.x;
    const int warpId = tid >> 5;
    const int warpRow = warpId >> 1;
    const int warpCol = warpId & 1;

    const int rowBase = blockIdx.y * BM;
    const int colBase = blockIdx.x * BN;

    const int KT = K / BK;

    auto load_stage_full = [&](int kt, int stage) {
        const __half* Ag = A + (size_t)rowBase * K + kt * BK;
        const __half* Bg = B + (size_t)(kt * BK) * N + colBase;
        __half* Asm = As + stage * A_STAGE;
        __half* Bsm = Bs + stage * B_STAGE;
        #pragma unroll
        for (int i = 0; i < 8; i++) {
            int l = tid + i * 128;
            int ar = l >> 3, ac = (l & 7) << 3;
            cp_async16(Asm + ar * A_LD + ac, Ag + (size_t)ar * K + ac);
        }
        #pragma unroll
        for (int i = 0; i < 8; i++) {
            int l = tid + i * 128;
            int br = l >> 4, bc = (l & 15) << 3;
            cp_async16(Bsm + br * B_LD + bc, Bg + (size_t)br * N + bc);
        }
        cp_commit();
    };

    auto load_stage_part = [&](int kt, int stage, int part) {
        __half* Asm = As + stage * A_STAGE;
        __half* Bsm = Bs + stage * B_STAGE;
        if (part < 2) {
            const __half* Ag = A + (size_t)rowBase * K + kt * BK;
            #pragma unroll
            for (int i = 0; i < 4; i++) {
                int l = tid + (part * 4 + i) * 128;
                int ar = l >> 3, ac = (l & 7) << 3;
                cp_async16(Asm + ar * A_LD + ac, Ag + (size_t)ar * K + ac);
            }
        } else {
            const __half* Bg = B + (size_t)(kt * BK) * N + colBase;
            #pragma unroll
            for (int i = 0; i < 4; i++) {
                int l = tid + ((part - 2) * 4 + i) * 128;
                int br = l >> 4, bc = (l & 15) << 3;
                cp_async16(Bsm + br * B_LD + bc, Bg + (size_t)br * N + bc);
            }
        }
    };

    load_stage_full(0, 0);
    load_stage_full(1, 1);

    wmma::fragment<wmma::accumulator, 16, 16, 16, float> acc[4][4];
    #pragma unroll
    for (int m = 0; m < 4; m++)
        #pragma unroll
        for (int n = 0; n < 4; n++)
            wmma::fill_fragment(acc[m][n], 0.0f);

    for (int kt = 0; kt < KT; kt++) {
        cp_wait<STAGES - 2>();
        __syncthreads();   // single barrier per K-tile

        const bool doLoad = (kt + STAGES - 1 < KT);
        const int  ldStage = (kt + STAGES - 1) % STAGES;

        const __half* Asm = As + (kt % STAGES) * A_STAGE;
        const __half* Bsm = Bs + (kt % STAGES) * B_STAGE;

        #pragma unroll
        for (int kk = 0; kk < BK / 16; kk++) {
            wmma::fragment<wmma::matrix_a, 16, 16, 16, __half, wmma::row_major> af[4];
            wmma::fragment<wmma::matrix_b, 16, 16, 16, __half, wmma::row_major> bf[4];
            #pragma unroll
            for (int m = 0; m < 4; m++)
                wmma::load_matrix_sync(af[m], Asm + (warpRow * 64 + m * 16) * A_LD + kk * 16, A_LD);
            #pragma unroll
            for (int n = 0; n < 4; n++)
                wmma::load_matrix_sync(bf[n], Bsm + (kk * 16) * B_LD + warpCol * 64 + n * 16, B_LD);

            if (doLoad)
                load_stage_part(kt + STAGES - 1, ldStage, kk);

            #pragma unroll
            for (int m = 0; m < 4; m++)
                #pragma unroll
                for (int n = 0; n < 4; n++)
                    wmma::mma_sync(acc[m][n], af[m], bf[n], acc[m][n]);
        }
        cp_commit();
    }

    #pragma unroll
    for (int m = 0; m < 4; m++) {
        #pragma unroll
        for (int n = 0; n < 4; n++) {
            int r = rowBase + warpRow * 64 + m * 16;
            int c = colBase + warpCol * 64 + n * 16;
            if constexpr (std::is_same<OutT, __half>::value) {
                wmma::fragment<wmma::accumulator, 16, 16, 16, __half> hacc;
                #pragma unroll
                for (int t = 0; t < hacc.num_elements; t++)
                    hacc.x[t] = __float2half_rn(acc[m][n].x[t]);
                wmma::store_matrix_sync(C + (size_t)r * N + c, hacc, N, wmma::mem_row_major);
            } else {
                wmma::store_matrix_sync(C + (size_t)r * N + c, acc[m][n], N, wmma::mem_row_major);
            }
        }
    }
}

// ---------------------------------------------------------------------------
// Elementwise fp32 -> fp16 (RN) conversion
// ---------------------------------------------------------------------------
__global__ void f32_to_f16_kernel(const float4* __restrict__ in,
                                  __half2* __restrict__ out, int n4)
{
    int i = blockIdx.x * blockDim.x + threadIdx.x;
    if (i < n4) {
        float4 v = in[i];
        out[2 * i]     = __floats2half2_rn(v.x, v.y);
        out[2 * i + 1] = __floats2half2_rn(v.z, v.w);
    }
}

// ---------------------------------------------------------------------------
// Per-token head-attention v3: 4 tokens per block (256 threads).
// fp16 qkv in, fp32 math, fp16 out. Dynamic smem, 4 CTAs/SM.
// All 24KB of the block's qkv loaded contiguously before one barrier (MLP=6).
// ---------------------------------------------------------------------------
#define QK_LD 17   // float4 stride for sq/sk rows
#define TB 4       // tokens per block
// dynamic smem layout (float4 units):
//   sq: TB * 16*QK_LD, sk: TB * 16*QK_LD, sv: TB * 256, then sattn: TB*256 floats
#define ATTN_SQ4   (16 * QK_LD)
#define ATTN_SMEM_BYTES ((TB * ATTN_SQ4 * 2 + TB * 256) * 16 + TB * 256 * 4)  // 55296

__global__ __launch_bounds__(256)
void attn_kernel(const __half* __restrict__ qkv, __half* __restrict__ out)
{
    extern __shared__ char asm_raw[];
    float4* sq    = reinterpret_cast<float4*>(asm_raw);                   // [TB][16*QK_LD]
    float4* sk    = sq + TB * ATTN_SQ4;                                   // [TB][16*QK_LD]
    float4* sv    = sk + TB * ATTN_SQ4;                                   // [TB][256]
    float*  sattn = reinterpret_cast<float*>(sv + TB * 256);              // [TB][256]

    const int t0 = blockIdx.x * TB;
    const uint4* base8 = reinterpret_cast<const uint4*>(qkv + (size_t)t0 * QKV_N);
    const int tid = threadIdx.x;

    // Load TB*384 = 1536 contiguous uint4 (6 per thread, all in flight pre-barrier)
    #pragma unroll
    for (int c = 0; c < 6; c++) {
        int idx8 = tid + c * 256;              // [0,1536)
        uint4 raw = base8[idx8];
        const __half2* h2 = reinterpret_cast<const __half2*>(&raw);
        float2 f0 = __half22float2(h2[0]);
        float2 f1 = __half22float2(h2[1]);
        float2 f2 = __half22float2(h2[2]);
        float2 f3 = __half22float2(h2[3]);
        float4 va = make_float4(f0.x, f0.y, f1.x, f1.y);
        float4 vb = make_float4(f2.x, f2.y, f3.x, f3.y);
        int tok = idx8 / 384;
        int rem = idx8 - tok * 384;
        int arr = rem >> 7;                    // 0=q,1=k,2=v
        int loc = rem & 127;
        int r   = loc >> 3;                    // row 0..15
        int d8  = loc & 7;                     // 8-half chunk
        if (arr == 0) {
            sq[tok * ATTN_SQ4 + r * QK_LD + d8 * 2]     = va;
            sq[tok * ATTN_SQ4 + r * QK_LD + d8 * 2 + 1] = vb;
        } else if (arr == 1) {
            sk[tok * ATTN_SQ4 + r * QK_LD + d8 * 2]     = va;
            sk[tok * ATTN_SQ4 + r * QK_LD + d8 * 2 + 1] = vb;
        } else {
            sv[tok * 256 + r * 16 + d8 * 2]     = va;
            sv[tok * 256 + r * 16 + d8 * 2 + 1] = vb;
        }
    }
    __syncthreads();

    // Scores + softmax for all TB tokens (independent shfl groups per token)
    const int i = tid >> 4, j = tid & 15;
    float sc[TB];
    #pragma unroll
    for (int tok = 0; tok < TB; tok++) {
        const float4* q4 = sq + tok * ATTN_SQ4 + i * QK_LD;
        const float4* k4 = sk + tok * ATTN_SQ4 + j * QK_LD;
        float s = 0.0f;
        #pragma unroll
        for (int d4 = 0; d4 < 16; d4++) {
            float4 a = q4[d4];
            float4 b = k4[d4];
            s += a.x * b.x + a.y * b.y + a.z * b.z + a.w * b.w;
        }
        sc[tok] = s * 0.125f;   // 1/sqrt(64)
    }
    #pragma unroll
    for (int tok = 0; tok < TB; tok++) {
        float s = sc[tok];
        float mx = s;
        #pragma unroll
        for (int off = 8; off; off >>= 1)
            mx = fmaxf(mx, __shfl_xor_sync(0xffffffffu, mx, off));
        float e = __expf(s - mx);
        float sum = e;
        #pragma unroll
        for (int off = 8; off; off >>= 1)
            sum += __shfl_xor_sync(0xffffffffu, sum, off);
        sattn[tok * 256 + i * 16 + j] = e / sum;
    }
    __syncthreads();

    // AV for all TB tokens
    const int oi = tid >> 4, od4 = tid & 15;
    #pragma unroll
    for (int tok = 0; tok < TB; tok++) {
        float4 acc = make_float4(0.f, 0.f, 0.f, 0.f);
        const float*  w4 = sattn + tok * 256 + oi * 16;
        const float4* v4 = sv + tok * 256;
        #pragma unroll
        for (int jj = 0; jj < 16; jj++) {
            float w = w4[jj];
            float4 v = v4[jj * 16 + od4];
            acc.x += w * v.x; acc.y += w * v.y;
            acc.z += w * v.z; acc.w += w * v.w;
        }
        __half2* o2 = reinterpret_cast<__half2*>(
            out + (size_t)(t0 + tok) * Dn + oi * 64 + od4 * 4);
        o2[0] = __floats2half2_rn(acc.x, acc.y);
        o2[1] = __floats2half2_rn(acc.z, acc.w);
    }
}

// ---------------------------------------------------------------------------
extern "C" void kernel_launch(void* const* d_in, const int* in_sizes, int n_in,
                              void* d_out, int out_size)
{
    const float* x    = (const float*)d_in[0];
    const float* Wqkv = (const float*)d_in[1];
    const float* Wout = (const float*)d_in[2];
    float* out = (float*)d_out;

    __half *qkvh_p, *attnh_p, *xh_p, *wqkvh_p, *wouth_p;
    cudaGetSymbolAddress((void**)&qkvh_p, g_qkvh);
    cudaGetSymbolAddress((void**)&attnh_p, g_attnh);
    cudaGetSymbolAddress((void**)&xh_p, g_xh);
    cudaGetSymbolAddress((void**)&wqkvh_p, g_wqkvh);
    cudaGetSymbolAddress((void**)&wouth_p, g_wouth);

    static bool attr_set = false;
    if (!attr_set) {
        cudaFuncSetAttribute(gemm_fp16_pipe_kernel<__half>,
                             cudaFuncAttributeMaxDynamicSharedMemorySize, SMEM_BYTES);
        cudaFuncSetAttribute(gemm_fp16_pipe_kernel<float>,
                             cudaFuncAttributeMaxDynamicSharedMemorySize, SMEM_BYTES);
        cudaFuncSetAttribute(attn_kernel,
                             cudaFuncAttributeMaxDynamicSharedMemorySize, ATTN_SMEM_BYTES);
        attr_set = true;
    }

    // Convert operands to fp16 (RN) once.
    {
        int n4x = (Mrows * Dn) / 4;
        f32_to_f16_kernel<<<(n4x + 255) / 256, 256>>>((const float4*)x, (__half2*)xh_p, n4x);
        int n4q = (Dn * QKV_N) / 4;
        f32_to_f16_kernel<<<(n4q + 255) / 256, 256>>>((const float4*)Wqkv, (__half2*)wqkvh_p, n4q);
        int n4o = (Dn * Dn) / 4;
        f32_to_f16_kernel<<<(n4o + 255) / 256, 256>>>((const float4*)Wout, (__half2*)wouth_p, n4o);
    }

    // GEMM1: qkv = x @ Wqkv   (16384 x 3072, K=1024), fp16 out
    {
        dim3 grid(QKV_N / BN, Mrows / BM);
        gemm_fp16_pipe_kernel<__half><<<grid, 128, SMEM_BYTES>>>(xh_p, wqkvh_p, qkvh_p,
                                                                 Mrows, QKV_N, Dn);
    }

    // Attention: 4 tokens per block
    attn_kernel<<<Mrows / TB, 256, ATTN_SMEM_BYTES>>>(qkvh_p, attnh_p);

    // GEMM2: out = attn @ Wout  (16384 x 1024, K=1024), fp32 out
    {
        dim3 grid(Dn / BN, Mrows / BM);
        gemm_fp16_pipe_kernel<float><<<grid, 128, SMEM_BYTES>>>(attnh_p, wouth_p, out,
                                                                Mrows, Dn, Dn);
    }
}

// round 14
// speedup vs baseline: 1.0990x; 1.0134x over previous
#include <cstdint>
#include <type_traits>
#include <cuda_runtime.h>
#include <cuda_fp16.h>
#include <mma.h>

using namespace nvcuda;

// Problem constants
#define Mrows 16384
#define QKV_N 3072
#define Dn 1024

// Scratch (device globals: allocation-free)
__device__ __half g_qkvh[(size_t)Mrows * QKV_N];   // 96 MB  (fp16 qkv)
__device__ __half g_attnh[(size_t)Mrows * Dn];     // 32 MB  (fp16 attention out)
__device__ __half g_xh[(size_t)Mrows * Dn];        // 32 MB  (fp16 x)
__device__ __half g_wqkvh[(size_t)Dn * QKV_N];     // 6 MB   (fp16 Wqkv)
__device__ __half g_wouth[(size_t)Dn * Dn];        // 2 MB   (fp16 Wout)

__device__ __forceinline__ void cp_async16(__half* smem_dst, const __half* gmem_src) {
    unsigned s = (unsigned)__cvta_generic_to_shared(smem_dst);
    asm volatile("cp.async.cg.shared.global [%0], [%1], 16;\n" :: "r"(s), "l"(gmem_src));
}
__device__ __forceinline__ void cp_commit() {
    asm volatile("cp.async.commit_group;\n" ::);
}
template<int N>
__device__ __forceinline__ void cp_wait() {
    asm volatile("cp.async.wait_group %0;\n" :: "n"(N));
}

// ---------------------------------------------------------------------------
// FP16 WMMA GEMM (fp32 accumulate), 3-stage cp.async pipeline.
// Block tile 128x128, BK=64, 4 warps (2x2), warp tile 64x64, 128 threads,
// 2 CTAs/SM. Single barrier per K-tile; cp.async interleaved with MMA.
// Inner loop reordered: bf first, then per-m af prefetch overlapping MMA rows.
// ---------------------------------------------------------------------------
#define BM 128
#define BN 128
#define BK 64
#define STAGES 3
#define A_LD (BK + 8)            // 72 halves
#define B_LD (BN + 8)            // 136 halves
#define A_STAGE (BM * A_LD)      // 9216 halves
#define B_STAGE (BK * B_LD)      // 8704 halves
#define SMEM_HALVES (STAGES * (A_STAGE + B_STAGE))
#define SMEM_BYTES (SMEM_HALVES * 2)   // 107520 B (x2 CTAs = 215KB < 228KB)

template<typename OutT>
__global__ __launch_bounds__(128, 2)
void gemm_fp16_pipe_kernel(const __half* __restrict__ A,
                           const __half* __restrict__ B,
                           OutT* __restrict__ C,
                           int M, int N, int K)
{
    extern __shared__ __half smem[];
    __half* As = smem;                         // [STAGES][BM][A_LD]
    __half* Bs = smem + STAGES * A_STAGE;      // [STAGES][BK][B_LD]

    const int tid = threadIdx.x;
    const int warpId = tid >> 5;
    const int warpRow = warpId >> 1;
    const int warpCol = warpId & 1;

    const int rowBase = blockIdx.y * BM;
    const int colBase = blockIdx.x * BN;

    const int KT = K / BK;

    auto load_stage_full = [&](int kt, int stage) {
        const __half* Ag = A + (size_t)rowBase * K + kt * BK;
        const __half* Bg = B + (size_t)(kt * BK) * N + colBase;
        __half* Asm = As + stage * A_STAGE;
        __half* Bsm = Bs + stage * B_STAGE;
        #pragma unroll
        for (int i = 0; i < 8; i++) {
            int l = tid + i * 128;
            int ar = l >> 3, ac = (l & 7) << 3;
            cp_async16(Asm + ar * A_LD + ac, Ag + (size_t)ar * K + ac);
        }
        #pragma unroll
        for (int i = 0; i < 8; i++) {
            int l = tid + i * 128;
            int br = l >> 4, bc = (l & 15) << 3;
            cp_async16(Bsm + br * B_LD + bc, Bg + (size_t)br * N + bc);
        }
        cp_commit();
    };

    auto load_stage_part = [&](int kt, int stage, int part) {
        __half* Asm = As + stage * A_STAGE;
        __half* Bsm = Bs + stage * B_STAGE;
        if (part < 2) {
            const __half* Ag = A + (size_t)rowBase * K + kt * BK;
            #pragma unroll
            for (int i = 0; i < 4; i++) {
                int l = tid + (part * 4 + i) * 128;
                int ar = l >> 3, ac = (l & 7) << 3;
                cp_async16(Asm + ar * A_LD + ac, Ag + (size_t)ar * K + ac);
            }
        } else {
            const __half* Bg = B + (size_t)(kt * BK) * N + colBase;
            #pragma unroll
            for (int i = 0; i < 4; i++) {
                int l = tid + ((part - 2) * 4 + i) * 128;
                int br = l >> 4, bc = (l & 15) << 3;
                cp_async16(Bsm + br * B_LD + bc, Bg + (size_t)br * N + bc);
            }
        }
    };

    load_stage_full(0, 0);
    load_stage_full(1, 1);

    wmma::fragment<wmma::accumulator, 16, 16, 16, float> acc[4][4];
    #pragma unroll
    for (int m = 0; m < 4; m++)
        #pragma unroll
        for (int n = 0; n < 4; n++)
            wmma::fill_fragment(acc[m][n], 0.0f);

    for (int kt = 0; kt < KT; kt++) {
        cp_wait<STAGES - 2>();
        __syncthreads();   // single barrier per K-tile

        const bool doLoad = (kt + STAGES - 1 < KT);
        const int  ldStage = (kt + STAGES - 1) % STAGES;

        const __half* Asm = As + (kt % STAGES) * A_STAGE;
        const __half* Bsm = Bs + (kt % STAGES) * B_STAGE;

        #pragma unroll
        for (int kk = 0; kk < BK / 16; kk++) {
            wmma::fragment<wmma::matrix_a, 16, 16, 16, __half, wmma::row_major> af[4];
            wmma::fragment<wmma::matrix_b, 16, 16, 16, __half, wmma::row_major> bf[4];

            // B fragments first, then the first A fragment
            #pragma unroll
            for (int n = 0; n < 4; n++)
                wmma::load_matrix_sync(bf[n], Bsm + (kk * 16) * B_LD + warpCol * 64 + n * 16, B_LD);
            wmma::load_matrix_sync(af[0], Asm + (warpRow * 64) * A_LD + kk * 16, A_LD);

            // cp.async quarter-stage between loads and math
            if (doLoad)
                load_stage_part(kt + STAGES - 1, ldStage, kk);

            // Row-m MMAs overlap the af[m+1] LDSM
            #pragma unroll
            for (int m = 0; m < 4; m++) {
                if (m + 1 < 4)
                    wmma::load_matrix_sync(af[m + 1],
                        Asm + (warpRow * 64 + (m + 1) * 16) * A_LD + kk * 16, A_LD);
                #pragma unroll
                for (int n = 0; n < 4; n++)
                    wmma::mma_sync(acc[m][n], af[m], bf[n], acc[m][n]);
            }
        }
        cp_commit();
    }

    #pragma unroll
    for (int m = 0; m < 4; m++) {
        #pragma unroll
        for (int n = 0; n < 4; n++) {
            int r = rowBase + warpRow * 64 + m * 16;
            int c = colBase + warpCol * 64 + n * 16;
            if constexpr (std::is_same<OutT, __half>::value) {
                wmma::fragment<wmma::accumulator, 16, 16, 16, __half> hacc;
                #pragma unroll
                for (int t = 0; t < hacc.num_elements; t++)
                    hacc.x[t] = __float2half_rn(acc[m][n].x[t]);
                wmma::store_matrix_sync(C + (size_t)r * N + c, hacc, N, wmma::mem_row_major);
            } else {
                wmma::store_matrix_sync(C + (size_t)r * N + c, acc[m][n], N, wmma::mem_row_major);
            }
        }
    }
}

// ---------------------------------------------------------------------------
// Fused fp32 -> fp16 (RN) conversion for x, Wqkv, Wout in ONE launch.
// Segments (in float4 units): x: 4.19M, Wqkv: 786K, Wout: 262K.
// ---------------------------------------------------------------------------
#define N4_X    ((Mrows * Dn) / 4)
#define N4_WQKV ((Dn * QKV_N) / 4)
#define N4_WOUT ((Dn * Dn) / 4)
#define N4_TOT  (N4_X + N4_WQKV + N4_WOUT)

__global__ void convert_all_kernel(const float4* __restrict__ x,
                                   const float4* __restrict__ wqkv,
                                   const float4* __restrict__ wout,
                                   __half2* __restrict__ xh,
                                   __half2* __restrict__ wqkvh,
                                   __half2* __restrict__ wouth)
{
    int i = blockIdx.x * blockDim.x + threadIdx.x;
    if (i >= N4_TOT) return;
    const float4* src; __half2* dst; int off;
    if (i < N4_X)                { src = x;    dst = xh;    off = i; }
    else if (i < N4_X + N4_WQKV) { src = wqkv; dst = wqkvh; off = i - N4_X; }
    else                         { src = wout; dst = wouth; off = i - N4_X - N4_WQKV; }
    float4 v = src[off];
    dst[2 * off]     = __floats2half2_rn(v.x, v.y);
    dst[2 * off + 1] = __floats2half2_rn(v.z, v.w);
}

// ---------------------------------------------------------------------------
// Per-token head-attention: 4 tokens per block (256 threads).
// fp16 qkv in, fp32 math, fp16 out.
// ---------------------------------------------------------------------------
#define QK_LD 17
#define TB 4
#define ATTN_SQ4   (16 * QK_LD)
#define ATTN_SMEM_BYTES ((TB * ATTN_SQ4 * 2 + TB * 256) * 16 + TB * 256 * 4)  // 55296

__global__ __launch_bounds__(256)
void attn_kernel(const __half* __restrict__ qkv, __half* __restrict__ out)
{
    extern __shared__ char asm_raw[];
    float4* sq    = reinterpret_cast<float4*>(asm_raw);
    float4* sk    = sq + TB * ATTN_SQ4;
    float4* sv    = sk + TB * ATTN_SQ4;
    float*  sattn = reinterpret_cast<float*>(sv + TB * 256);

    const int t0 = blockIdx.x * TB;
    const uint4* base8 = reinterpret_cast<const uint4*>(qkv + (size_t)t0 * QKV_N);
    const int tid = threadIdx.x;

    #pragma unroll
    for (int c = 0; c < 6; c++) {
        int idx8 = tid + c * 256;
        uint4 raw = base8[idx8];
        const __half2* h2 = reinterpret_cast<const __half2*>(&raw);
        float2 f0 = __half22float2(h2[0]);
        float2 f1 = __half22float2(h2[1]);
        float2 f2 = __half22float2(h2[2]);
        float2 f3 = __half22float2(h2[3]);
        float4 va = make_float4(f0.x, f0.y, f1.x, f1.y);
        float4 vb = make_float4(f2.x, f2.y, f3.x, f3.y);
        int tok = idx8 / 384;
        int rem = idx8 - tok * 384;
        int arr = rem >> 7;
        int loc = rem & 127;
        int r   = loc >> 3;
        int d8  = loc & 7;
        if (arr == 0) {
            sq[tok * ATTN_SQ4 + r * QK_LD + d8 * 2]     = va;
            sq[tok * ATTN_SQ4 + r * QK_LD + d8 * 2 + 1] = vb;
        } else if (arr == 1) {
            sk[tok * ATTN_SQ4 + r * QK_LD + d8 * 2]     = va;
            sk[tok * ATTN_SQ4 + r * QK_LD + d8 * 2 + 1] = vb;
        } else {
            sv[tok * 256 + r * 16 + d8 * 2]     = va;
            sv[tok * 256 + r * 16 + d8 * 2 + 1] = vb;
        }
    }
    __syncthreads();

    const int i = tid >> 4, j = tid & 15;
    float sc[TB];
    #pragma unroll
    for (int tok = 0; tok < TB; tok++) {
        const float4* q4 = sq + tok * ATTN_SQ4 + i * QK_LD;
        const float4* k4 = sk + tok * ATTN_SQ4 + j * QK_LD;
        float s = 0.0f;
        #pragma unroll
        for (int d4 = 0; d4 < 16; d4++) {
            float4 a = q4[d4];
            float4 b = k4[d4];
            s += a.x * b.x + a.y * b.y + a.z * b.z + a.w * b.w;
        }
        sc[tok] = s * 0.125f;
    }
    #pragma unroll
    for (int tok = 0; tok < TB; tok++) {
        float s = sc[tok];
        float mx = s;
        #pragma unroll
        for (int off = 8; off; off >>= 1)
            mx = fmaxf(mx, __shfl_xor_sync(0xffffffffu, mx, off));
        float e = __expf(s - mx);
        float sum = e;
        #pragma unroll
        for (int off = 8; off; off >>= 1)
            sum += __shfl_xor_sync(0xffffffffu, sum, off);
        sattn[tok * 256 + i * 16 + j] = e / sum;
    }
    __syncthreads();

    const int oi = tid >> 4, od4 = tid & 15;
    #pragma unroll
    for (int tok = 0; tok < TB; tok++) {
        float4 acc = make_float4(0.f, 0.f, 0.f, 0.f);
        const float*  w4 = sattn + tok * 256 + oi * 16;
        const float4* v4 = sv + tok * 256;
        #pragma unroll
        for (int jj = 0; jj < 16; jj++) {
            float w = w4[jj];
            float4 v = v4[jj * 16 + od4];
            acc.x += w * v.x; acc.y += w * v.y;
            acc.z += w * v.z; acc.w += w * v.w;
        }
        __half2* o2 = reinterpret_cast<__half2*>(
            out + (size_t)(t0 + tok) * Dn + oi * 64 + od4 * 4);
        o2[0] = __floats2half2_rn(acc.x, acc.y);
        o2[1] = __floats2half2_rn(acc.z, acc.w);
    }
}

// ---------------------------------------------------------------------------
extern "C" void kernel_launch(void* const* d_in, const int* in_sizes, int n_in,
                              void* d_out, int out_size)
{
    const float* x    = (const float*)d_in[0];
    const float* Wqkv = (const float*)d_in[1];
    const float* Wout = (const float*)d_in[2];
    float* out = (float*)d_out;

    __half *qkvh_p, *attnh_p, *xh_p, *wqkvh_p, *wouth_p;
    cudaGetSymbolAddress((void**)&qkvh_p, g_qkvh);
    cudaGetSymbolAddress((void**)&attnh_p, g_attnh);
    cudaGetSymbolAddress((void**)&xh_p, g_xh);
    cudaGetSymbolAddress((void**)&wqkvh_p, g_wqkvh);
    cudaGetSymbolAddress((void**)&wouth_p, g_wouth);

    static bool attr_set = false;
    if (!attr_set) {
        cudaFuncSetAttribute(gemm_fp16_pipe_kernel<__half>,
                             cudaFuncAttributeMaxDynamicSharedMemorySize, SMEM_BYTES);
        cudaFuncSetAttribute(gemm_fp16_pipe_kernel<float>,
                             cudaFuncAttributeMaxDynamicSharedMemorySize, SMEM_BYTES);
        cudaFuncSetAttribute(attn_kernel,
                             cudaFuncAttributeMaxDynamicSharedMemorySize, ATTN_SMEM_BYTES);
        attr_set = true;
    }

    // One fused conversion launch for all operands
    convert_all_kernel<<<(N4_TOT + 255) / 256, 256>>>(
        (const float4*)x, (const float4*)Wqkv, (const float4*)Wout,
        (__half2*)xh_p, (__half2*)wqkvh_p, (__half2*)wouth_p);

    // GEMM1: qkv = x @ Wqkv   (16384 x 3072, K=1024), fp16 out
    {
        dim3 grid(QKV_N / BN, Mrows / BM);
        gemm_fp16_pipe_kernel<__half><<<grid, 128, SMEM_BYTES>>>(xh_p, wqkvh_p, qkvh_p,
                                                                 Mrows, QKV_N, Dn);
    }

    // Attention: 4 tokens per block
    attn_kernel<<<Mrows / TB, 256, ATTN_SMEM_BYTES>>>(qkvh_p, attnh_p);

    // GEMM2: out = attn @ Wout  (16384 x 1024, K=1024), fp32 out
    {
        dim3 grid(Dn / BN, Mrows / BM);
        gemm_fp16_pipe_kernel<float><<<grid, 128, SMEM_BYTES>>>(attnh_p, wouth_p, out,
                                                                Mrows, Dn, Dn);
    }
}